// round 6
// baseline (speedup 1.0000x reference)
#include <cuda_runtime.h>
#include <cuda_fp16.h>
#include <cstdint>

typedef unsigned long long u64;
typedef uint32_t u32;

#define NB 4096
#define NE 16
#define ND 512
#define NH 2048

#define KC 64                          // k-chunk: 64 fp16 = 128B rows
#define TILE 16384                     // 128 x 64 fp16 tile bytes
#define STAGE (2 * TILE)               // xh, wh
#define NSTAGE 5
#define OFF_STAGES 8192                // after d-table (16*128 floats)
#define SMEM_TOTAL (OFF_STAGES + NSTAGE * STAGE)   // 172032 B

// ---------------- scratch (device globals; no allocations allowed) ----------
__device__ __half g_xh[NB * ND];
__device__ __half g_wh[NE * NH * ND];
__device__ float  g_dcomb[NE * NH];

// ---------------- PTX helpers ----------------------------------------------
__device__ __forceinline__ u32 smem_u32(const void* p) {
    u32 a;
    asm("{ .reg .u64 t; cvta.to.shared.u64 t, %1; cvt.u32.u64 %0, t; }" : "=r"(a) : "l"(p));
    return a;
}
__device__ __forceinline__ void cp16(u32 dst, const void* src) {
    asm volatile("cp.async.cg.shared.global [%0], [%1], 16;" :: "r"(dst), "l"(src) : "memory");
}
__device__ __forceinline__ void cp_commit() { asm volatile("cp.async.commit_group;" ::: "memory"); }
__device__ __forceinline__ void cp_wait3()  { asm volatile("cp.async.wait_group 3;" ::: "memory"); }

__device__ __forceinline__ void ldsm4(u32& r0, u32& r1, u32& r2, u32& r3, u32 addr) {
    asm volatile("ldmatrix.sync.aligned.m8n8.x4.shared.b16 {%0,%1,%2,%3}, [%4];"
                 : "=r"(r0), "=r"(r1), "=r"(r2), "=r"(r3) : "r"(addr));
}
// fp16-accumulate MMA: C/D fragment = 2 x u32 (4 halves)
__device__ __forceinline__ void mma16816h(u32* c, const u32* a, const u32* b) {
    asm volatile("mma.sync.aligned.m16n8k16.row.col.f16.f16.f16.f16 "
                 "{%0,%1}, {%2,%3,%4,%5}, {%6,%7}, {%0,%1};"
                 : "+r"(c[0]), "+r"(c[1])
                 : "r"(a[0]), "r"(a[1]), "r"(a[2]), "r"(a[3]), "r"(b[0]), "r"(b[1]));
}

__device__ __forceinline__ u32 swz128(u32 off) { return off ^ ((off >> 3) & 0x70); }

// ---------------- prep kernels ----------------------------------------------
__global__ void x_conv_kernel(const float* __restrict__ x) {
    int i = blockIdx.x * blockDim.x + threadIdx.x;
    float4 v = ((const float4*)x)[i];
    __half2* ph = (__half2*)g_xh;
    ph[2 * i]     = __half2(__float2half_rn(v.x), __float2half_rn(v.y));
    ph[2 * i + 1] = __half2(__float2half_rn(v.z), __float2half_rn(v.w));
}

// one warp per (e,h) row: W row -> fp16, and d = bias - c_e . W_row (fp32)
__global__ void w_conv_bias_kernel(const float* __restrict__ W,
                                   const float* __restrict__ centers,
                                   const float* __restrict__ bias) {
    int gw   = (blockIdx.x * blockDim.x + threadIdx.x) >> 5;
    int lane = threadIdx.x & 31;
    if (gw >= NE * NH) return;
    int e = gw >> 11;
    const float4* wr = (const float4*)(W + (size_t)gw * ND);
    const float4* cr = (const float4*)(centers + (size_t)e * ND);
    __half2* ph = (__half2*)(g_wh + (size_t)gw * ND);
    float s = 0.f;
#pragma unroll
    for (int i = 0; i < ND / 128; i++) {
        int idx = lane + 32 * i;
        float4 w4 = wr[idx];
        float4 c4 = cr[idx];
        s += w4.x * c4.x + w4.y * c4.y + w4.z * c4.z + w4.w * c4.w;
        ph[2 * idx]     = __half2(__float2half_rn(w4.x), __float2half_rn(w4.y));
        ph[2 * idx + 1] = __half2(__float2half_rn(w4.z), __float2half_rn(w4.w));
    }
#pragma unroll
    for (int o = 16; o; o >>= 1) s += __shfl_xor_sync(0xffffffffu, s, o);
    if (lane == 0) g_dcomb[gw] = bias[gw] - s;
}

// ---------------- main GEMM kernel -------------------------------------------
// grid (NH/128, NB/128) = (16, 32); 256 threads, 8 warps (2m x 4n of 64x32).
// 128 chunks = 16 experts x 8 k-chunks of 64.
// fp16-acc MMA within a chunk; promote to fp32 per chunk; relu per expert.

__device__ __forceinline__ void load_chunk(int gc, u32 dst, int mb, int hb, int tid) {
    int e = gc >> 3, kc = (gc & 7) * KC;
    int row = tid >> 3, c = tid & 7;
    u32 so = swz128((u32)(row * 128 + c * 16));
    const __half* pxh = g_xh + (size_t)(mb + row) * ND + kc + c * 8;
    const __half* pwh = g_wh + (size_t)(e * NH + hb + row) * ND + kc + c * 8;
#pragma unroll
    for (int i = 0; i < 4; i++) {
        u32 d = dst + so + (u32)i * 4096;          // +32 rows per step
        size_t eo = (size_t)(32 * i) * ND;
        cp16(d + 0 * TILE, pxh + eo);
        cp16(d + 1 * TILE, pwh + eo);
    }
}

__global__ void __launch_bounds__(256, 1)
gemm_kernel(float* __restrict__ out) {
    extern __shared__ char smem[];
    float* dsm = (float*)smem;                     // [16][128] combined bias
    u32 sb = smem_u32(smem) + OFF_STAGES;
    const int tid = threadIdx.x, wid = tid >> 5, lane = tid & 31;
    const int hb = blockIdx.x * 128, mb = blockIdx.y * 128;
    const int wm = (wid >> 2) * 64, wn = (wid & 3) * 32;

    // stage the per-expert combined bias slice for this CTA
#pragma unroll
    for (int i = tid; i < NE * 128; i += 256)
        dsm[i] = g_dcomb[(size_t)(i >> 7) * NH + hb + (i & 127)];

    load_chunk(0, sb + 0 * STAGE, mb, hb, tid); cp_commit();
    load_chunk(1, sb + 1 * STAGE, mb, hb, tid); cp_commit();
    load_chunk(2, sb + 2 * STAGE, mb, hb, tid); cp_commit();
    load_chunk(3, sb + 3 * STAGE, mb, hb, tid); cp_commit();

    u32   acc16[4][4][2];                          // fp16x2 chunk accumulators
    float accf [4][4][4];                          // fp32 per-expert accumulators
    float oacc [4][4][4];                          // fp32 relu-sum accumulators
#pragma unroll
    for (int a = 0; a < 4; a++)
#pragma unroll
        for (int b = 0; b < 4; b++) {
#pragma unroll
            for (int c = 0; c < 4; c++) { accf[a][b][c] = 0.f; oacc[a][b][c] = 0.f; }
            acc16[a][b][0] = 0u; acc16[a][b][1] = 0u;
        }

    int st_idx = 0, pf_idx = 4;
    for (int gc = 0; gc < 128; gc++) {
        cp_wait3();
        __syncthreads();

        // issue next prefetch FIRST so cp.async overlaps with this chunk's math.
        if (gc + 4 < 128) load_chunk(gc + 4, sb + (u32)pf_idx * STAGE, mb, hb, tid);
        cp_commit();
        pf_idx = (pf_idx == NSTAGE - 1) ? 0 : pf_idx + 1;

        u32 st = sb + (u32)st_idx * STAGE;
        st_idx = (st_idx == NSTAGE - 1) ? 0 : st_idx + 1;
        u32 Ah = st, Bh = st + TILE;

#pragma unroll
        for (int ks = 0; ks < 4; ks++) {
            u32 ah[4][4], bh[4][2];
            u32 arel = swz128((u32)((lane & 15) * 128 + ks * 32 + (lane >> 4) * 16));
#pragma unroll
            for (int mt = 0; mt < 4; mt++) {
                u32 ao = (u32)((wm + mt * 16) * 128) + arel;
                ldsm4(ah[mt][0], ah[mt][1], ah[mt][2], ah[mt][3], Ah + ao);
            }
            u32 brel = swz128((u32)((lane & 7) * 128 + ks * 32 + ((lane >> 3) & 1) * 16));
#pragma unroll
            for (int pr = 0; pr < 2; pr++) {
                u32 bo = (u32)((wn + pr * 16 + ((lane >> 4) & 1) * 8) * 128) + brel;
                ldsm4(bh[pr * 2][0], bh[pr * 2][1], bh[pr * 2 + 1][0], bh[pr * 2 + 1][1], Bh + bo);
            }
#pragma unroll
            for (int mt = 0; mt < 4; mt++)
#pragma unroll
                for (int nt = 0; nt < 4; nt++)
                    mma16816h(acc16[mt][nt], ah[mt], bh[nt]);
        }

        // promote chunk's fp16 partials into fp32 accumulators, reset fp16 acc
#pragma unroll
        for (int mt = 0; mt < 4; mt++)
#pragma unroll
            for (int nt = 0; nt < 4; nt++) {
                float2 p0 = __half22float2(*(__half2*)&acc16[mt][nt][0]);
                float2 p1 = __half22float2(*(__half2*)&acc16[mt][nt][1]);
                accf[mt][nt][0] += p0.x;
                accf[mt][nt][1] += p0.y;
                accf[mt][nt][2] += p1.x;
                accf[mt][nt][3] += p1.y;
                acc16[mt][nt][0] = 0u;
                acc16[mt][nt][1] = 0u;
            }

        if ((gc & 7) == 7) {    // finished expert e: relu + accumulate, reset
            int e = gc >> 3;
            const float2* dp = (const float2*)(dsm + e * 128 + wn);
#pragma unroll
            for (int nt = 0; nt < 4; nt++) {
                float2 d2 = dp[nt * 4 + (lane & 3)];
#pragma unroll
                for (int mt = 0; mt < 4; mt++) {
                    oacc[mt][nt][0] += fmaxf(accf[mt][nt][0] + d2.x, 0.f);
                    oacc[mt][nt][1] += fmaxf(accf[mt][nt][1] + d2.y, 0.f);
                    oacc[mt][nt][2] += fmaxf(accf[mt][nt][2] + d2.x, 0.f);
                    oacc[mt][nt][3] += fmaxf(accf[mt][nt][3] + d2.y, 0.f);
                    accf[mt][nt][0] = 0.f; accf[mt][nt][1] = 0.f;
                    accf[mt][nt][2] = 0.f; accf[mt][nt][3] = 0.f;
                }
            }
        }
    }

    // store: C fragment mapping — (row t/4 [+8], col 2*(t%4) [+1])
#pragma unroll
    for (int mt = 0; mt < 4; mt++)
#pragma unroll
        for (int nt = 0; nt < 4; nt++) {
            int r0 = mb + wm + mt * 16 + (lane >> 2);
            int cc = hb + wn + nt * 8 + 2 * (lane & 3);
            *(float2*)(out + (size_t)r0 * NH + cc) =
                make_float2(oacc[mt][nt][0], oacc[mt][nt][1]);
            *(float2*)(out + (size_t)(r0 + 8) * NH + cc) =
                make_float2(oacc[mt][nt][2], oacc[mt][nt][3]);
        }
}

// ---------------- launch -----------------------------------------------------
extern "C" void kernel_launch(void* const* d_in, const int* in_sizes, int n_in,
                              void* d_out, int out_size) {
    const float* x       = (const float*)d_in[0];  // [B, D]
    const float* centers = (const float*)d_in[1];  // [E, D]
    const float* W       = (const float*)d_in[2];  // [E, H, D]
    const float* bias    = (const float*)d_in[3];  // [E, H]
    float* out = (float*)d_out;                    // [B, H]

    cudaFuncSetAttribute(gemm_kernel, cudaFuncAttributeMaxDynamicSharedMemorySize, SMEM_TOTAL);

    x_conv_kernel<<<(NB * ND / 4) / 256, 256>>>(x);
    w_conv_bias_kernel<<<(NE * NH) / 8, 256>>>(W, centers, bias);

    dim3 grid(NH / 128, NB / 128);   // (16, 32)
    gemm_kernel<<<grid, 256, SMEM_TOTAL>>>(out);
}